// round 10
// baseline (speedup 1.0000x reference)
#include <cuda_runtime.h>
#include <cuda_fp16.h>
#include <math.h>

// ---------------------------------------------------------------------------
// DTree forward. Round 10: periphery attack (k6 is at the legacy-HMMA floor).
// - prep_leaf: smem-staged, fully coalesced (was 4x sector over-fetch)
// - k34: k1b2 + k3 + k4 fused (h512/invh prologue, mma, smem right-tile,
//   routing/entropy epilogue). g_right eliminated. 4 launches total.
// ---------------------------------------------------------------------------

#define BATCH   8192
#define DIN     512
#define D1      513
#define HP      272      // g_hh row stride in u32 (half2 pairs): 544 halves
#define NKT     17
#define NODES   127
#define LEAVES  128
#define DOUT    256
#define ITERS   (NKT * LEAVES)   // 2176

// prep_all block ranges
#define PB_LEAF (LEAVES * NKT)   // 2176 tile blocks
#define PB_PRE  512
#define PB_RW   136
#define PB_NORM NODES

typedef unsigned long long u64;
typedef unsigned int u32;

// -------------------- scratch (device globals; no allocation) --------------
__device__ __align__(16) u32 g_hh[BATCH * HP];          // 8.9 MB packed half2 h
__device__ __align__(16) u32 g_Bp[LEAVES * NKT * 4096]; // 35.7 MB leaf B fragments
__device__ __align__(16) u32 g_Bpre[16 * 8192];         // 0.52 MB W_pre fragments
__device__ __align__(16) u32 g_Brw[NKT * 2048];         // 0.14 MB right_w fragments
__device__ u32 g_swh2[LEAVES * BATCH];                  // 4.2 MB (s,s) half2
__device__ float g_invw[NODES];
__device__ float g_entpart[128];

// -------------------- helpers ----------------------------------------------
__device__ __forceinline__ u32 h2(float lo, float hi) {
    u32 r; asm("cvt.rn.f16x2.f32 %0, %1, %2;" : "=r"(r) : "f"(hi), "f"(lo)); return r;
}
__device__ __forceinline__ u32 hmul2(u32 a, u32 b) {
    u32 r; asm("mul.f16x2 %0, %1, %2;" : "=r"(r) : "r"(a), "r"(b)); return r;
}
__device__ __forceinline__ float2 h2f(u32 v) {
    __half2 h = *reinterpret_cast<__half2*>(&v);
    return __half22float2(h);
}
__device__ __forceinline__ void mma_f16(float* c, u32 a0, u32 a1, u32 a2, u32 a3,
                                        u32 b0, u32 b1) {
    asm volatile("mma.sync.aligned.m16n8k16.row.col.f32.f16.f16.f32 "
                 "{%0,%1,%2,%3}, {%4,%5,%6,%7}, {%8,%9}, {%0,%1,%2,%3};"
                 : "+f"(c[0]), "+f"(c[1]), "+f"(c[2]), "+f"(c[3])
                 : "r"(a0), "r"(a1), "r"(a2), "r"(a3), "r"(b0), "r"(b1));
}

// Fragment addressing convention (m16n8k16):
//   B frag u32 index = (((tile*NW + nw)*2 + ks)*2 + h)*128 + lane*4 + r
//   nt = h*2 + (r>>1); reg = r&1
//   n  = nw*32 + nt*8 + (lane>>2)
//   d  = kt*32 + ks*16 + (lane&3)*2 + reg*8   (value = half2(W[n][d], W[n][d+1]))

// ============================================================================
// k_prep_all: all weight preprocessing in one launch.
//   blocks [0, 2176): leaf fragment tile (l, kt), smem-staged & coalesced
//   then W_pre fragments, right_w fragments, right_w norms (as before)
// ============================================================================
__global__ void k_prep_all(const float* __restrict__ Wl, const float* __restrict__ bl,
                           const float* __restrict__ Wp, const float* __restrict__ rw) {
    int blk = blockIdx.x;
    int tid = threadIdx.x;
    if (blk < PB_LEAF) {
        __shared__ float s_w[256][33];
        int l = blk / NKT, kt = blk % NKT;
        // stage 256 rows x 32 cols, coalesced 128B row chunks
        for (int e = tid; e < 256 * 32; e += 256) {
            int rt = e >> 5, c = e & 31;
            int d = kt * 32 + c;
            int row = l * 256 + rt;
            float v = 0.0f;
            if (d < D1)       v = Wl[(size_t)row * D1 + d];
            else if (d == D1) v = bl[row];
            s_w[rt][c] = v;
        }
        __syncthreads();
        u32* dst = g_Bp + (size_t)blk * 4096;
        #pragma unroll
        for (int i = 0; i < 16; i++) {
            u32 o = (u32)tid + i * 256;             // 0..4095, coalesced store
            u32 r = o & 3, lane = (o >> 2) & 31;
            u32 h = (o >> 7) & 1, ks = (o >> 8) & 1, nw = (o >> 9) & 7;
            u32 nt = h * 2 + (r >> 1), reg = r & 1;
            int n = (int)(nw * 32 + nt * 8 + (lane >> 2));
            int c = (int)(ks * 16 + (lane & 3) * 2 + reg * 8);
            dst[o] = h2(s_w[n][c], s_w[n][c + 1]);
        }
        return;
    }
    blk -= PB_LEAF;
    if (blk < PB_PRE) {
        u32 o = (u32)blk * 256 + tid;   // < 131072
        u32 r = o & 3, lane = (o >> 2) & 31;
        u32 h = (o >> 7) & 1, ks = (o >> 8) & 1, nw = (o >> 9) & 15;
        u32 kt = o >> 13;
        u32 nt = h * 2 + (r >> 1), reg = r & 1;
        int n = (int)(nw * 32 + nt * 8 + (lane >> 2));
        int d = (int)(kt * 32 + ks * 16 + (lane & 3) * 2 + reg * 8);
        g_Bpre[o] = h2(Wp[(size_t)n * DIN + d], Wp[(size_t)n * DIN + d + 1]);
        return;
    }
    blk -= PB_PRE;
    if (blk < PB_RW) {
        u32 o = (u32)blk * 256 + tid;   // < 34816
        u32 r = o & 3, lane = (o >> 2) & 31;
        u32 h = (o >> 7) & 1, ks = (o >> 8) & 1, nw = (o >> 9) & 3;
        u32 kt = o >> 11;
        u32 nt = h * 2 + (r >> 1), reg = r & 1;
        int n = (int)(nw * 32 + nt * 8 + (lane >> 2));
        int d = (int)(kt * 32 + ks * 16 + (lane & 3) * 2 + reg * 8);
        float v0 = (n < NODES && d < D1)     ? rw[(size_t)n * D1 + d]     : 0.0f;
        float v1 = (n < NODES && d + 1 < D1) ? rw[(size_t)n * D1 + d + 1] : 0.0f;
        g_Brw[o] = h2(v0, v1);
        return;
    }
    blk -= PB_RW;
    {   // inverse row norm for node blk
        __shared__ float sm[8];
        int n = blk;
        const float* wr = rw + (size_t)n * D1;
        float s = 0.0f;
        for (int d = tid; d < D1; d += 256) { float v = wr[d]; s += v * v; }
        #pragma unroll
        for (int o = 16; o > 0; o >>= 1) s += __shfl_xor_sync(0xffffffffu, s, o);
        if ((tid & 31) == 0) sm[tid >> 5] = s;
        __syncthreads();
        if (tid == 0) {
            float t = 0.0f;
            #pragma unroll
            for (int i = 0; i < 8; i++) t += sm[i];
            g_invw[n] = 1.0f / fmaxf(sqrtf(t), 1e-12f);
        }
    }
}

// ============================================================================
// k1: h[:,0:512] = relu(x @ W_pre[0:512]^T + b_pre) -> g_hh pairs 0..255
// ============================================================================
__global__ __launch_bounds__(256, 1) void k1_pre(const float* __restrict__ x,
                                                 const float* __restrict__ bp) {
    int tid = threadIdx.x, wid = tid >> 5, lane = tid & 31;
    int mw = wid >> 2, nwl = wid & 3;
    int m0 = blockIdx.y * 128;
    int nw = blockIdx.x * 4 + nwl;
    int rbase = m0 + mw * 64 + (lane >> 2);

    const u32* Bb = g_Bpre + (size_t)nw * 512 + lane * 4;
    const float* Xb = x + (size_t)rbase * DIN + (lane & 3) * 2;

    float acc[4][4][4];
    #pragma unroll
    for (int a = 0; a < 4; a++)
        #pragma unroll
        for (int b = 0; b < 4; b++)
            #pragma unroll
            for (int c = 0; c < 4; c++) acc[a][b][c] = 0.0f;

    uint4 bb[2][2][2];
    #pragma unroll
    for (int ks = 0; ks < 2; ks++)
        #pragma unroll
        for (int h = 0; h < 2; h++)
            bb[0][ks][h] = __ldg((const uint4*)(Bb + ks * 256 + h * 128));

    #pragma unroll 2
    for (int kt = 0; kt < 16; kt++) {
        int pb = kt & 1, nb = pb ^ 1;
        if (kt + 1 < 16) {
            const u32* t = Bb + (size_t)(kt + 1) * 8192;
            #pragma unroll
            for (int ks = 0; ks < 2; ks++)
                #pragma unroll
                for (int h = 0; h < 2; h++)
                    bb[nb][ks][h] = __ldg((const uint4*)(t + ks * 256 + h * 128));
        }
        u32 av[4][2][2][2];
        #pragma unroll
        for (int mt = 0; mt < 4; mt++)
            #pragma unroll
            for (int rhl = 0; rhl < 2; rhl++)
                #pragma unroll
                for (int ks = 0; ks < 2; ks++)
                    #pragma unroll
                    for (int reg = 0; reg < 2; reg++) {
                        float2 f = *(const float2*)(Xb + (size_t)(mt * 16 + rhl * 8) * DIN
                                                    + kt * 32 + ks * 16 + reg * 8);
                        av[mt][rhl][ks][reg] = h2(f.x, f.y);
                    }
        #pragma unroll
        for (int ks = 0; ks < 2; ks++)
            #pragma unroll
            for (int h = 0; h < 2; h++) {
                uint4 B = bb[pb][ks][h];
                #pragma unroll
                for (int mt = 0; mt < 4; mt++) {
                    mma_f16(acc[mt][h * 2],     av[mt][0][ks][0], av[mt][1][ks][0],
                            av[mt][0][ks][1], av[mt][1][ks][1], B.x, B.y);
                    mma_f16(acc[mt][h * 2 + 1], av[mt][0][ks][0], av[mt][1][ks][0],
                            av[mt][0][ks][1], av[mt][1][ks][1], B.z, B.w);
                }
            }
    }

    int ncol = blockIdx.x * 128 + nwl * 32 + (lane & 3) * 2;
    #pragma unroll
    for (int mt = 0; mt < 4; mt++)
        #pragma unroll
        for (int half = 0; half < 2; half++) {
            int row = rbase + mt * 16 + half * 8;
            #pragma unroll
            for (int nt = 0; nt < 4; nt++) {
                int n = ncol + nt * 8;
                float v0 = fmaxf(acc[mt][nt][half * 2]     + __ldg(bp + n),     0.0f);
                float v1 = fmaxf(acc[mt][nt][half * 2 + 1] + __ldg(bp + n + 1), 0.0f);
                g_hh[(size_t)row * HP + (n >> 1)] = h2(v0, v1);
            }
        }
}

// ============================================================================
// k34: fused k1b2 + k3 + k4. 128 CTAs x 128 thr, CTA owns rows m0..m0+63.
//   Prologue: h512 + pad writes + invh for own rows (2 threads per row).
//   MMA: right-tile = (h . right_w) via fp16 mma (reads own fresh pads).
//   Epilogue: right tile -> smem; routing, s_w (g_swh2), entropy partial.
// ============================================================================
__global__ __launch_bounds__(128, 2) void k34(const float* __restrict__ x,
                                              const float* __restrict__ Wp,
                                              const float* __restrict__ bp,
                                              const int* __restrict__ ridx,
                                              const int* __restrict__ rside) {
    __shared__ float s_right[64][129];
    __shared__ int   s_idx[LEAVES * 7];
    __shared__ int   s_side[LEAVES * 7];
    __shared__ float s_lr[4][128];
    __shared__ float s_ll[4][128];
    __shared__ float s_invh[64];
    __shared__ float s_ent[4];

    int tid = threadIdx.x, w = tid >> 5, lane = tid & 31;
    int m0 = blockIdx.x * 64;

    for (int t = tid; t < LEAVES * 7; t += 128) { s_idx[t] = ridx[t]; s_side[t] = rside[t]; }

    // ---- prologue: 2 threads per row ----
    {
        int rl = tid >> 1, hs = tid & 1;
        int row = m0 + rl;
        const float* xr = x + (size_t)row * DIN + hs * 256;
        const float* wr = Wp + (size_t)512 * DIN + hs * 256;
        float s = 0.0f;
        #pragma unroll 4
        for (int d = 0; d < 256; d++) s += xr[d] * wr[d];
        s += __shfl_xor_sync(0xffffffffu, s, 1);
        float h512 = fmaxf(s + __ldg(bp + 512), 0.0f);

        const u32* hr = g_hh + (size_t)row * HP + hs * 128;
        float t2 = 0.0f;
        #pragma unroll 4
        for (int i = 0; i < 128; i++) {
            float2 f = h2f(hr[i]);
            t2 += f.x * f.x + f.y * f.y;
        }
        t2 += __shfl_xor_sync(0xffffffffu, t2, 1);

        u32* rowp = g_hh + (size_t)row * HP;
        if (hs == 0) {
            rowp[256] = h2(h512, 1.0f);
            s_invh[rl] = 1.0f / fmaxf(sqrtf(t2 + h512 * h512), 1e-12f);
        } else {
            #pragma unroll
            for (int i = 0; i < 15; i++) rowp[257 + i] = 0u;
        }
    }
    __syncthreads();

    // ---- mma: right tile (64m x 128n), one warp per 32-col n-slice ----
    int rbase = m0 + (lane >> 2);
    const u32* Bb = g_Brw + (size_t)w * 512 + lane * 4;
    const u32* Hb = g_hh + (size_t)rbase * HP + (lane & 3);

    float acc[4][4][4];
    #pragma unroll
    for (int a = 0; a < 4; a++)
        #pragma unroll
        for (int b = 0; b < 4; b++)
            #pragma unroll
            for (int c = 0; c < 4; c++) acc[a][b][c] = 0.0f;

    #pragma unroll 1
    for (int kt = 0; kt < 17; kt++) {
        uint4 bb[2][2];
        #pragma unroll
        for (int ks = 0; ks < 2; ks++)
            #pragma unroll
            for (int h = 0; h < 2; h++)
                bb[ks][h] = __ldg((const uint4*)(Bb + (size_t)kt * 2048 + ks * 256 + h * 128));
        u32 hv[4][2][2][2];
        #pragma unroll
        for (int mt = 0; mt < 4; mt++)
            #pragma unroll
            for (int rhl = 0; rhl < 2; rhl++)
                #pragma unroll
                for (int ks = 0; ks < 2; ks++)
                    #pragma unroll
                    for (int reg = 0; reg < 2; reg++)
                        hv[mt][rhl][ks][reg] = __ldg(Hb + (size_t)(mt * 16 + rhl * 8) * HP
                                                     + kt * 16 + ks * 8 + reg * 4);
        #pragma unroll
        for (int ks = 0; ks < 2; ks++)
            #pragma unroll
            for (int h = 0; h < 2; h++) {
                uint4 B = bb[ks][h];
                #pragma unroll
                for (int mt = 0; mt < 4; mt++) {
                    mma_f16(acc[mt][h * 2],     hv[mt][0][ks][0], hv[mt][1][ks][0],
                            hv[mt][0][ks][1], hv[mt][1][ks][1], B.x, B.y);
                    mma_f16(acc[mt][h * 2 + 1], hv[mt][0][ks][0], hv[mt][1][ks][0],
                            hv[mt][0][ks][1], hv[mt][1][ks][1], B.z, B.w);
                }
            }
    }

    // scale by invh*invw, stash in smem right tile
    #pragma unroll
    for (int mt = 0; mt < 4; mt++)
        #pragma unroll
        for (int half = 0; half < 2; half++) {
            int rl = (lane >> 2) + mt * 16 + half * 8;
            float ih = s_invh[rl];
            #pragma unroll
            for (int nt = 0; nt < 4; nt++) {
                int n = w * 32 + nt * 8 + (lane & 3) * 2;
                if (n < NODES)
                    s_right[rl][n] = acc[mt][nt][half * 2] * ih * g_invw[n];
                if (n + 1 < NODES)
                    s_right[rl][n + 1] = acc[mt][nt][half * 2 + 1] * ih * g_invw[n + 1];
            }
        }
    __syncthreads();

    // ---- routing + s_w + entropy: each warp handles 16 rows ----
    float ent = 0.0f;
    for (int rr = 0; rr < 16; rr++) {
        int rl = w * 16 + rr;
        for (int n = lane; n < NODES; n += 32) {
            float r = s_right[rl][n];
            float rd = 0.5f * (1.0f - r);
            float ld = 0.5f * (1.0f + r);
            s_lr[w][n] = logf(fminf(fmaxf(rd, 0.01f), 0.99f));
            s_ll[w][n] = logf(fminf(fmaxf(ld, 0.01f), 0.99f));
        }
        __syncwarp();
        for (int li = lane; li < LEAVES; li += 32) {
            float lp = 0.0f;
            #pragma unroll
            for (int j = 0; j < 7; j++) {
                int node = s_idx[li * 7 + j];
                int side = s_side[li * 7 + j];
                lp += side ? s_ll[w][node] : s_lr[w][node];
            }
            float s = expf(lp);
            g_swh2[li * BATCH + m0 + rl] = h2(s, s);
            ent -= s * lp;
        }
        __syncwarp();
    }
    #pragma unroll
    for (int o = 16; o > 0; o >>= 1) ent += __shfl_xor_sync(0xffffffffu, ent, o);
    if (lane == 0) s_ent[w] = ent;
    __syncthreads();
    if (tid == 0) {
        g_entpart[blockIdx.x] = s_ent[0] + s_ent[1] + s_ent[2] + s_ent[3];
    }
}

// ============================================================================
// k6: fp16 mma leaf contraction. 256 CTAs x 128 thr, CTA tile 128m x 64n
// (2 n-slice warps x 2 m-half warps; m-pair B loads dedup in L1).
// Scale reduction from g_entpart[128] inline in epilogue (deterministic).
// ============================================================================
__global__ __launch_bounds__(128, 2) void k6_mma(float* __restrict__ out) {
    int tid = threadIdx.x, wid = tid >> 5, lane = tid & 31;
    int mw = wid >> 1, nwl = wid & 1;
    int m0 = blockIdx.y * 128;
    int nw = blockIdx.x * 2 + nwl;
    int rbase = m0 + mw * 64 + (lane >> 2);

    const u32* Bb = g_Bp + (size_t)nw * 512 + lane * 4;     // + tile*4096 (+ks*256+h*128)
    const u32* SWb = g_swh2 + rbase;
    const u32* Hb = g_hh + (size_t)rbase * HP + (lane & 3);

    float acc[4][4][4];
    #pragma unroll
    for (int a = 0; a < 4; a++)
        #pragma unroll
        for (int b = 0; b < 4; b++)
            #pragma unroll
            for (int c = 0; c < 4; c++) acc[a][b][c] = 0.0f;

    uint4 bb[2][2][2];       // [buf][ks][h]
    u32 sw[2][8];            // [buf][mt*2 + rhl]
    u32 hv[4][2][2][2];      // [mt][rhl][ks][reg]

    // preload it=0 (kt=0, l=0)
    #pragma unroll
    for (int ks = 0; ks < 2; ks++)
        #pragma unroll
        for (int h = 0; h < 2; h++)
            bb[0][ks][h] = __ldg((const uint4*)(Bb + ks * 256 + h * 128));
    #pragma unroll
    for (int j = 0; j < 8; j++)
        sw[0][j] = __ldg(SWb + (j >> 1) * 16 + (j & 1) * 8);

    int it = 0;
    #pragma unroll 1
    for (int kt = 0; kt < NKT; kt++) {
        #pragma unroll
        for (int mt = 0; mt < 4; mt++)
            #pragma unroll
            for (int rhl = 0; rhl < 2; rhl++)
                #pragma unroll
                for (int ks = 0; ks < 2; ks++)
                    #pragma unroll
                    for (int reg = 0; reg < 2; reg++)
                        hv[mt][rhl][ks][reg] = __ldg(Hb + (size_t)(mt * 16 + rhl * 8) * HP
                                                     + kt * 16 + ks * 8 + reg * 4);
        #pragma unroll 2
        for (int l = 0; l < LEAVES; l++) {
            int pb = l & 1, nb = pb ^ 1;
            int nit = it + 1;
            if (nit < ITERS) {
                int nl = nit & 127, nkt = nit >> 7;
                const u32* t = Bb + (size_t)(nl * 17 + nkt) * 4096;
                #pragma unroll
                for (int ks = 0; ks < 2; ks++)
                    #pragma unroll
                    for (int h = 0; h < 2; h++)
                        bb[nb][ks][h] = __ldg((const uint4*)(t + ks * 256 + h * 128));
                const u32* sp = SWb + (size_t)nl * BATCH;
                #pragma unroll
                for (int j = 0; j < 8; j++)
                    sw[nb][j] = __ldg(sp + (j >> 1) * 16 + (j & 1) * 8);
            }
            #pragma unroll
            for (int ks = 0; ks < 2; ks++) {
                u32 A0[4], A1[4], A2[4], A3[4];
                #pragma unroll
                for (int mt = 0; mt < 4; mt++) {
                    A0[mt] = hmul2(hv[mt][0][ks][0], sw[pb][mt * 2]);
                    A1[mt] = hmul2(hv[mt][1][ks][0], sw[pb][mt * 2 + 1]);
                    A2[mt] = hmul2(hv[mt][0][ks][1], sw[pb][mt * 2]);
                    A3[mt] = hmul2(hv[mt][1][ks][1], sw[pb][mt * 2 + 1]);
                }
                #pragma unroll
                for (int h = 0; h < 2; h++) {
                    uint4 B = bb[pb][ks][h];
                    #pragma unroll
                    for (int mt = 0; mt < 4; mt++) {
                        mma_f16(acc[mt][h * 2],     A0[mt], A1[mt], A2[mt], A3[mt], B.x, B.y);
                        mma_f16(acc[mt][h * 2 + 1], A0[mt], A1[mt], A2[mt], A3[mt], B.z, B.w);
                    }
                }
            }
            it++;
        }
    }

    // inline deterministic scale = 1 + (sum(entpart)/BATCH)/max_ent
    __shared__ float sm[128];
    sm[tid] = g_entpart[tid];
    __syncthreads();
    #pragma unroll
    for (int st = 64; st > 0; st >>= 1) {
        if (tid < st) sm[tid] += sm[tid + st];
        __syncthreads();
    }
    float max_ent = (128.0f / 6.0f) * logf(6.0f);
    float sc = 1.0f + (sm[0] / (float)BATCH) / max_ent;

    int ncol = blockIdx.x * 64 + nwl * 32 + (lane & 3) * 2;
    #pragma unroll
    for (int mt = 0; mt < 4; mt++)
        #pragma unroll
        for (int half = 0; half < 2; half++) {
            int row = rbase + mt * 16 + half * 8;
            float* op = out + (size_t)row * DOUT + ncol;
            #pragma unroll
            for (int nt = 0; nt < 4; nt++) {
                float2 v;
                v.x = acc[mt][nt][half * 2] * sc;
                v.y = acc[mt][nt][half * 2 + 1] * sc;
                *(float2*)(op + nt * 8) = v;
            }
        }
}

// ============================================================================
extern "C" void kernel_launch(void* const* d_in, const int* in_sizes, int n_in,
                              void* d_out, int out_size) {
    const float* x      = (const float*)d_in[0];
    const float* W_pre  = (const float*)d_in[1];
    const float* b_pre  = (const float*)d_in[2];
    const float* rw     = (const float*)d_in[3];
    const float* W_leaf = (const float*)d_in[4];
    const float* b_leaf = (const float*)d_in[5];
    const int*   ridx   = (const int*)d_in[6];
    const int*   rside  = (const int*)d_in[7];
    float* out = (float*)d_out;

    k_prep_all<<<PB_LEAF + PB_PRE + PB_RW + PB_NORM, 256>>>(W_leaf, b_leaf, W_pre, rw);
    k1_pre<<<dim3(4, 64), 256>>>(x, b_pre);
    k34<<<128, 128>>>(x, W_pre, b_pre, ridx, rside);
    k6_mma<<<dim3(4, 64), 128>>>(out);
}